// round 2
// baseline (speedup 1.0000x reference)
#include <cuda_runtime.h>
#include <math_constants.h>

// CropProposals: 3D ROI 2x2x2 adaptive max-pool.
// fm:      (4, 64, 24, 24, 24) f32   -> d_in[0]
// corners: (4, 64, 2, 3)       f32   -> d_in[1]
// out:     (4, 64, 64, 2, 2, 2) f32
//
// One warp per (b, p, c). Lanes span W (contiguous). Per-lane accumulators for
// the 2x2 (kx,ky) bins; h-loop folded into 2 row maxes first (2 FMAX/voxel).
// Final 2 z-bins via butterfly shfl max.

#define NEGINF (-CUDART_INF_F)

__global__ __launch_bounds__(256) void crop_proposals_kernel(
    const float* __restrict__ fm,
    const float* __restrict__ corners,
    float* __restrict__ out)
{
    const int warp = blockIdx.x * 8 + (threadIdx.x >> 5);   // 0 .. 16383
    const int lane = threadIdx.x & 31;

    const int c  = warp & 63;        // channel
    const int bp = warp >> 6;        // b*64 + p   (0..255)

    // ---- bin computation (matches JAX _pool_masks exactly, fp32) ----
    const float* cor = corners + bp * 6;   // [2][3]
    int blo[3][2], bhi[3][2];
#pragma unroll
    for (int a = 0; a < 3; a++) {
        float ll = cor[a]     * 0.25f;
        float ur = cor[3 + a] * 0.25f;
        ll = fminf(fmaxf(ll, 0.0f), 21.0f);
        ur = (ur - ll >= 2.0f) ? ur : (ll + 2.0f);
        ur = fminf(fmaxf(ur, 2.0f), 23.0f);
        int lo = (int)floorf(ll);
        int n  = (int)floorf(ur) - lo;
        blo[a][0] = lo;              bhi[a][0] = lo + ((n + 1) >> 1);
        blo[a][1] = lo + (n >> 1);   bhi[a][1] = lo + n;
    }

    const float* base = fm + ((size_t)((bp >> 6) * 64 + c)) * 13824;  // b*64+c volumes

    // z (W axis) membership for this lane; union of the two z-bins = [blo_z0, bhi_z1)
    const bool zact = (lane >= blo[2][0]) && (lane < bhi[2][1]);

    float acc00 = NEGINF, acc01 = NEGINF, acc10 = NEGINF, acc11 = NEGINF;

    const int d0 = blo[0][0], d1 = bhi[0][1];
    const int h0 = blo[1][0], h1 = bhi[1][1];
    const int x0hi = bhi[0][0], x1lo = blo[0][1];
    const int y0hi = bhi[1][0], y1lo = blo[1][1];

    for (int d = d0; d < d1; d++) {
        const bool inx0 = (d < x0hi);
        const bool inx1 = (d >= x1lo);
        float r0 = NEGINF, r1 = NEGINF;
        const float* row = base + d * 576 + h0 * 24 + lane;
        for (int h = h0; h < h1; h++) {
            float v = zact ? __ldg(row) : NEGINF;
            row += 24;
            if (h < y0hi)  r0 = fmaxf(r0, v);
            if (h >= y1lo) r1 = fmaxf(r1, v);
        }
        if (inx0) { acc00 = fmaxf(acc00, r0); acc01 = fmaxf(acc01, r1); }
        if (inx1) { acc10 = fmaxf(acc10, r0); acc11 = fmaxf(acc11, r1); }
    }

    // ---- z-bin reductions across lanes (butterfly) ----
#pragma unroll
    for (int kz = 0; kz < 2; kz++) {
        const bool inz = (lane >= blo[2][kz]) && (lane < bhi[2][kz]);
        float m00 = inz ? acc00 : NEGINF;
        float m01 = inz ? acc01 : NEGINF;
        float m10 = inz ? acc10 : NEGINF;
        float m11 = inz ? acc11 : NEGINF;
#pragma unroll
        for (int off = 16; off; off >>= 1) {
            m00 = fmaxf(m00, __shfl_xor_sync(0xFFFFFFFFu, m00, off));
            m01 = fmaxf(m01, __shfl_xor_sync(0xFFFFFFFFu, m01, off));
            m10 = fmaxf(m10, __shfl_xor_sync(0xFFFFFFFFu, m10, off));
            m11 = fmaxf(m11, __shfl_xor_sync(0xFFFFFFFFu, m11, off));
        }
        if (lane == 0) {
            float* o = out + ((size_t)warp << 3) + kz;
            o[0] = m00;   // kx=0, ky=0
            o[2] = m01;   // kx=0, ky=1
            o[4] = m10;   // kx=1, ky=0
            o[6] = m11;   // kx=1, ky=1
        }
    }
}

extern "C" void kernel_launch(void* const* d_in, const int* in_sizes, int n_in,
                              void* d_out, int out_size)
{
    const float* fm      = (const float*)d_in[0];
    const float* corners = (const float*)d_in[1];
    float* out           = (float*)d_out;

    // 4*64*64 = 16384 warps, 8 warps/block -> 2048 blocks
    crop_proposals_kernel<<<2048, 256>>>(fm, corners, out);
}